// round 7
// baseline (speedup 1.0000x reference)
#include <cuda_runtime.h>
#include <math.h>
#include <stdint.h>

#define Bc   64
#define Sc   512
#define Dc   512
#define Hc   8
#define DKc  64
#define Lc   4
#define DFFc 2048
#define NSKc 300
#define NSKp 384
#define FC1c 512
#define FC2c 256
#define Mr   (Bc * Sc)
#define QM   16256.0f   // 127*128

// ---------------- fp32 scratch ----------------
__device__ float g_qe [(size_t)Mr * Dc];
__device__ float g_x  [(size_t)Mr * Dc];
__device__ float g_K  [(size_t)Mr * Dc];
__device__ float g_V  [(size_t)Mr * Dc];
__device__ float g_P  [(size_t)Mr * Dc];
__device__ float g_O  [(size_t)Mr * Dc];
__device__ float g_F1f[(size_t)Mr * DFFc];
__device__ float g_H1f[(size_t)Mr * FC1c];
__device__ float g_H2f[(size_t)Mr * FC2c];

// ---------------- int8 activations (hi/lo) + row scales ----------------
__device__ int8_t g_xqh [(size_t)Mr * Dc],     g_xql [(size_t)Mr * Dc];
__device__ int8_t g_yqh [(size_t)Mr * Dc],     g_yql [(size_t)Mr * Dc];
__device__ int8_t g_Oqh [(size_t)Mr * Dc],     g_Oql [(size_t)Mr * Dc];
__device__ int8_t g_F1qh[(size_t)Mr * DFFc],   g_F1ql[(size_t)Mr * DFFc];
__device__ int8_t g_Cqh [(size_t)Mr * 2 * Dc], g_Cql [(size_t)Mr * 2 * Dc];
__device__ int8_t g_H1qh[(size_t)Mr * FC1c],   g_H1ql[(size_t)Mr * FC1c];
__device__ int8_t g_H2qh[(size_t)Mr * FC2c],   g_H2ql[(size_t)Mr * FC2c];
__device__ float g_sx[Mr], g_sy[Mr], g_sOr[Mr], g_sF1[Mr], g_sC[Mr],
                 g_sH1[Mr], g_sH2[Mr];

// ---------------- int8 weights [N][K] (hi/lo) + col scales ----------------
__device__ int8_t g_Wk_h[(size_t)Lc * Dc * Dc],   g_Wk_l[(size_t)Lc * Dc * Dc];
__device__ int8_t g_Wv_h[(size_t)Lc * Dc * Dc],   g_Wv_l[(size_t)Lc * Dc * Dc];
__device__ int8_t g_Wo_h[(size_t)Lc * Dc * Dc],   g_Wo_l[(size_t)Lc * Dc * Dc];
__device__ int8_t g_W1_h[(size_t)Lc * Dc * DFFc], g_W1_l[(size_t)Lc * Dc * DFFc];
__device__ int8_t g_W2_h[(size_t)Lc * DFFc * Dc], g_W2_l[(size_t)Lc * DFFc * Dc];
__device__ int8_t g_Wo1_h[(size_t)2 * Dc * FC1c], g_Wo1_l[(size_t)2 * Dc * FC1c];
__device__ int8_t g_Wo2_h[(size_t)FC1c * FC2c],   g_Wo2_l[(size_t)FC1c * FC2c];
__device__ int8_t g_Wo3_h[(size_t)NSKp * FC2c],   g_Wo3_l[(size_t)NSKp * FC2c];
__device__ float g_sW[32768], g_iW[32768];

// scale-buffer offsets
#define OFF_WK  0
#define OFF_WV  2048
#define OFF_WO  4096
#define OFF_W1  6144
#define OFF_W2  14336
#define OFF_WO1 16384
#define OFF_WO2 16896
#define OFF_WO3 17152

// ---------------- helpers ----------------
__device__ __forceinline__ uint32_t smem_u32(const void* p) {
    uint32_t a;
    asm("{ .reg .u64 t; cvta.to.shared.u64 t, %1; cvt.u32.u64 %0, t; }"
        : "=r"(a) : "l"(p));
    return a;
}
__device__ __forceinline__ void q2(float v, float inv, int8_t& h, int8_t& l) {
    int q = __float2int_rn(v * inv);
    int qh = (q + 64) >> 7;
    h = (int8_t)qh;
    l = (int8_t)(q - (qh << 7));
}
__device__ __forceinline__ float blockmax256(float v, float* sb, int tid) {
    #pragma unroll
    for (int o = 16; o > 0; o >>= 1)
        v = fmaxf(v, __shfl_xor_sync(0xffffffffu, v, o));
    if ((tid & 31) == 0) sb[tid >> 5] = v;
    __syncthreads();
    if (tid < 32) {
        float m = (tid < 8) ? sb[tid] : 0.f;
        #pragma unroll
        for (int o = 4; o > 0; o >>= 1)
            m = fmaxf(m, __shfl_xor_sync(0xffffffffu, m, o));
        if (tid == 0) sb[0] = m;
    }
    __syncthreads();
    return sb[0];
}

#define CPA16(dst, src)                                                       \
    asm volatile("cp.async.cg.shared.global [%0], [%1], 16;"                  \
                 :: "r"(dst), "l"(src) : "memory")

#define LDMX4(R, addr)                                                        \
    asm volatile("ldmatrix.sync.aligned.m8n8.x4.shared.b16 {%0,%1,%2,%3}, [%4];" \
        : "=r"((R)[0]), "=r"((R)[1]), "=r"((R)[2]), "=r"((R)[3]) : "r"(addr))

#define LDMX2(R, addr)                                                        \
    asm volatile("ldmatrix.sync.aligned.m8n8.x2.shared.b16 {%0,%1}, [%2];"    \
        : "=r"((R)[0]), "=r"((R)[1]) : "r"(addr))

#define IMMA16832(d, a, b)                                                    \
    asm volatile("mma.sync.aligned.m16n8k32.row.col.s32.s8.s8.s32 "           \
        "{%0,%1,%2,%3}, {%4,%5,%6,%7}, {%8,%9}, {%0,%1,%2,%3};"               \
        : "+r"((d)[0]), "+r"((d)[1]), "+r"((d)[2]), "+r"((d)[3])              \
        : "r"((a)[0]), "r"((a)[1]), "r"((a)[2]), "r"((a)[3]),                 \
          "r"((b)[0]), "r"((b)[1]))

// ---------------- weight prep ----------------
__global__ void wcolmax_kernel(const float* __restrict__ W, int K, int N,
                               int Npad, float* __restrict__ s,
                               float* __restrict__ si) {
    int n = blockIdx.x * 256 + threadIdx.x;
    if (n >= Npad) return;
    float m = 0.f;
    if (n < N)
        for (int k = 0; k < K; k++)
            m = fmaxf(m, fabsf(W[(size_t)k * N + n]));
    s[n]  = m * (1.f / QM);
    si[n] = (m > 0.f) ? QM / m : 0.f;
}

__global__ void wquant_kernel(const float* __restrict__ W,
                              int8_t* __restrict__ Qh, int8_t* __restrict__ Ql,
                              const float* __restrict__ si, int K, int N) {
    __shared__ float t[32][33];
    int k0 = blockIdx.y * 32, n0 = blockIdx.x * 32;
    #pragma unroll
    for (int i = 0; i < 4; i++) {
        int k = k0 + threadIdx.y + i * 8;
        int n = n0 + threadIdx.x;
        t[threadIdx.y + i * 8][threadIdx.x] = (n < N) ? W[(size_t)k * N + n] : 0.f;
    }
    __syncthreads();
    #pragma unroll
    for (int i = 0; i < 4; i++) {
        int n = n0 + threadIdx.y + i * 8;
        int k = k0 + threadIdx.x;
        int8_t h, l;
        q2(t[threadIdx.x][threadIdx.y + i * 8], si[n], h, l);
        Qh[(size_t)n * K + k] = h;
        Ql[(size_t)n * K + k] = l;
    }
}

// ---------------- generic per-row quantizer ----------------
__global__ __launch_bounds__(256)
void rowquant_kernel(const float* __restrict__ X, int8_t* __restrict__ Qh,
                     int8_t* __restrict__ Ql, float* __restrict__ srow,
                     int ncols) {
    __shared__ float sb[8];
    const int row = blockIdx.x, tid = threadIdx.x;
    const size_t base = (size_t)row * ncols;
    float m = 0.f;
    for (int c = tid; c < ncols; c += 256)
        m = fmaxf(m, fabsf(X[base + c]));
    m = blockmax256(m, sb, tid);
    const float inv = (m > 0.f) ? QM / m : 0.f;
    for (int c = tid; c < ncols; c += 256) {
        int8_t h, l;
        q2(X[base + c], inv, h, l);
        Qh[base + c] = h;
        Ql[base + c] = l;
    }
    if (tid == 0) srow[row] = m * (1.f / QM);
}

// ---------------- split-int8 IMMA GEMM ----------------
// A int8 pairs [M][K] + row scale; W int8 pairs [Npad][K] + col scale.
// CTA 128x128, K-tile 64, 8 warps (2m x 4n), 2-stage cp.async, one sync/iter.
#define APITCH 80                  // bytes/row: 64 data + 16 pad
#define TILE_B (128 * APITCH)      // 10240
#define STAGE_B (4 * TILE_B)       // 40960
#define GEMM_DSMEM (2 * STAGE_B)   // 81920

__device__ __forceinline__ void issue_stage(
    uint32_t sb, const int8_t* Ah_g, const int8_t* Al_g,
    const int8_t* Bh_g, const int8_t* Bl_g,
    int m0, int n0, int K, int kk, int tid) {
    #pragma unroll
    for (int p = 0; p < 2; p++) {
        int c = p * 256 + tid;
        int row = c >> 2, q = c & 3;
        uint32_t d = sb + (uint32_t)(row * APITCH + q * 16);
        size_t ao = (size_t)(m0 + row) * K + kk + q * 16;
        size_t bo = (size_t)(n0 + row) * K + kk + q * 16;
        CPA16(d,              Ah_g + ao);
        CPA16(d + TILE_B,     Al_g + ao);
        CPA16(d + 2 * TILE_B, Bh_g + bo);
        CPA16(d + 3 * TILE_B, Bl_g + bo);
    }
    asm volatile("cp.async.commit_group;" ::: "memory");
}

__global__ __launch_bounds__(256, 1)
void gemm_i8_kernel(const int8_t* __restrict__ Aqh, const int8_t* __restrict__ Aql,
                    const float* __restrict__ sA,
                    const int8_t* __restrict__ Bqh, const int8_t* __restrict__ Bql,
                    const float* __restrict__ sB,
                    const float* __restrict__ bias, float* __restrict__ C,
                    int K, int N, int relu) {
    extern __shared__ char smem[];
    const int tid  = threadIdx.x;
    const int wid  = tid >> 5;
    const int lane = tid & 31;
    const int m0 = blockIdx.y * 128;
    const int n0 = blockIdx.x * 128;
    const int warp_m = (wid >> 2) * 64;
    const int warp_n = (wid & 3) * 32;
    const uint32_t sbase = smem_u32(smem);

    int acc1[4][4][4], acc2[4][4][4];
    #pragma unroll
    for (int i = 0; i < 4; i++)
        #pragma unroll
        for (int j = 0; j < 4; j++)
            #pragma unroll
            for (int e = 0; e < 4; e++) { acc1[i][j][e] = 0; acc2[i][j][e] = 0; }

    const int KT = K >> 6;
    const int r8  = lane & 7;
    const int sub = lane >> 3;
    const uint32_t a_lane_off =
        (uint32_t)((warp_m + r8 + (sub & 1) * 8) * APITCH + (sub >> 1) * 16);
    const uint32_t b_lane_off =
        (uint32_t)((warp_n + r8) * APITCH + (sub & 1) * 16);

    issue_stage(sbase, Aqh, Aql, Bqh, Bql, m0, n0, K, 0, tid);

    for (int kt = 0; kt < KT; kt++) {
        asm volatile("cp.async.wait_group 0;" ::: "memory");
        __syncthreads();
        if (kt + 1 < KT)
            issue_stage(sbase + ((kt + 1) & 1) * STAGE_B, Aqh, Aql, Bqh, Bql,
                        m0, n0, K, (kt + 1) << 6, tid);

        const uint32_t stoff = (kt & 1) * STAGE_B;
        const uint32_t abase = sbase + stoff + a_lane_off;
        const uint32_t bbase = sbase + stoff + 2 * TILE_B + b_lane_off;

        #pragma unroll
        for (int ks = 0; ks < 2; ks++) {
            const uint32_t ak = abase + ks * 32;   // 32 int8 of K
            const uint32_t bk = bbase + ks * 32;

            uint32_t Ahf[4][4], Bhf[4][2];
            #pragma unroll
            for (int fi = 0; fi < 4; fi++)
                LDMX4(Ahf[fi], ak + fi * (16 * APITCH));
            #pragma unroll
            for (int fj = 0; fj < 4; fj++)
                LDMX2(Bhf[fj], bk + fj * (8 * APITCH));
            #pragma unroll
            for (int fi = 0; fi < 4; fi++)
                #pragma unroll
                for (int fj = 0; fj < 4; fj++)
                    IMMA16832(acc1[fi][fj], Ahf[fi], Bhf[fj]);

            uint32_t Blf[4][2];
            #pragma unroll
            for (int fj = 0; fj < 4; fj++)
                LDMX2(Blf[fj], bk + TILE_B + fj * (8 * APITCH));
            #pragma unroll
            for (int fi = 0; fi < 4; fi++)
                #pragma unroll
                for (int fj = 0; fj < 4; fj++)
                    IMMA16832(acc2[fi][fj], Ahf[fi], Blf[fj]);

            uint32_t Alf[4][4];
            #pragma unroll
            for (int fi = 0; fi < 4; fi++)
                LDMX4(Alf[fi], ak + TILE_B + fi * (16 * APITCH));
            #pragma unroll
            for (int fi = 0; fi < 4; fi++)
                #pragma unroll
                for (int fj = 0; fj < 4; fj++)
                    IMMA16832(acc2[fi][fj], Alf[fi], Bhf[fj]);
        }
    }

    // epilogue: dequant + bias (+relu), fp32 out
    #pragma unroll
    for (int fj = 0; fj < 4; fj++) {
        const int c0 = n0 + warp_n + fj * 8 + 2 * (lane & 3);
        const bool c0ok = (c0 < N), c1ok = (c0 + 1 < N);
        const float sb0 = c0ok ? sB[c0] : 0.f;
        const float sb1 = c1ok ? sB[c0 + 1] : 0.f;
        const float b0 = c0ok ? bias[c0] : 0.f;
        const float b1 = c1ok ? bias[c0 + 1] : 0.f;
        #pragma unroll
        for (int fi = 0; fi < 4; fi++) {
            const int r0 = m0 + warp_m + fi * 16 + (lane >> 2);
            const float sa0 = sA[r0], sa1 = sA[r0 + 8];
            float v0 = (16384.f * (float)acc1[fi][fj][0] +
                        128.f * (float)acc2[fi][fj][0]) * (sa0 * sb0) + b0;
            float v1 = (16384.f * (float)acc1[fi][fj][1] +
                        128.f * (float)acc2[fi][fj][1]) * (sa0 * sb1) + b1;
            float v2 = (16384.f * (float)acc1[fi][fj][2] +
                        128.f * (float)acc2[fi][fj][2]) * (sa1 * sb0) + b0;
            float v3 = (16384.f * (float)acc1[fi][fj][3] +
                        128.f * (float)acc2[fi][fj][3]) * (sa1 * sb1) + b1;
            if (relu) {
                v0 = fmaxf(v0, 0.f); v1 = fmaxf(v1, 0.f);
                v2 = fmaxf(v2, 0.f); v3 = fmaxf(v3, 0.f);
            }
            if (c0ok) {
                C[(size_t)r0 * N + c0]       = v0;
                C[(size_t)(r0 + 8) * N + c0] = v2;
            }
            if (c1ok) {
                C[(size_t)r0 * N + c0 + 1]       = v1;
                C[(size_t)(r0 + 8) * N + c0 + 1] = v3;
            }
        }
    }
}

// ---------------- embed (row-block, fused quantize) ----------------
__global__ __launch_bounds__(256)
void embed_kernel(const int* __restrict__ q_data, const int* __restrict__ target,
                  const float* __restrict__ pe, const float* __restrict__ q_emb,
                  const float* __restrict__ qa_emb) {
    __shared__ float sb1[8], sb2[8];
    const int row = blockIdx.x, tid = threadIdx.x;
    const int s = row % Sc;
    const int qd = q_data[row], tg = target[row];
    const size_t base = (size_t)row * Dc;

    float qe0 = q_emb[(size_t)qd * Dc + tid];
    float qe1 = q_emb[(size_t)qd * Dc + tid + 256];
    float x0 = qe0 + pe[(size_t)s * Dc + tid];
    float x1 = qe1 + pe[(size_t)s * Dc + tid + 256];
    float y0 = qa_emb[(size_t)tg * Dc + tid] + x0;
    float y1 = qa_emb[(size_t)tg * Dc + tid + 256] + x1;
    g_qe[base + tid] = qe0;       g_qe[base + tid + 256] = qe1;
    g_x [base + tid] = x0;        g_x [base + tid + 256] = x1;

    float mx = blockmax256(fmaxf(fabsf(x0), fabsf(x1)), sb1, tid);
    float my = blockmax256(fmaxf(fabsf(y0), fabsf(y1)), sb2, tid);
    float ix = (mx > 0.f) ? QM / mx : 0.f;
    float iy = (my > 0.f) ? QM / my : 0.f;
    int8_t h, l;
    q2(x0, ix, h, l); g_xqh[base + tid] = h;       g_xql[base + tid] = l;
    q2(x1, ix, h, l); g_xqh[base + tid + 256] = h; g_xql[base + tid + 256] = l;
    q2(y0, iy, h, l); g_yqh[base + tid] = h;       g_yql[base + tid] = l;
    q2(y1, iy, h, l); g_yqh[base + tid + 256] = h; g_yql[base + tid + 256] = l;
    if (tid == 0) { g_sx[row] = mx * (1.f / QM); g_sy[row] = my * (1.f / QM); }
}

// ---------------- flash attention (fp32 in/out) ----------------
__global__ __launch_bounds__(256)
void attn_kernel() {
    const int qt = blockIdx.x, hh = blockIdx.y, b = blockIdx.z;
    const int tid = threadIdx.x;
    const int r = tid >> 2;
    const int p = tid & 3;
    const int i = qt * 64 + r;
    const float scale = 0.125f;

    __shared__ float Kt[64][64];
    __shared__ float Vt[64][64];

    float q[16];
    {
        const float* qp = g_K + ((size_t)(b * Sc + i)) * Dc + hh * DKc + p * 16;
        #pragma unroll
        for (int w = 0; w < 4; w++) {
            float4 v = *(const float4*)(qp + w * 4);
            q[w * 4 + 0] = v.x; q[w * 4 + 1] = v.y;
            q[w * 4 + 2] = v.z; q[w * 4 + 3] = v.w;
        }
    }

    float m_run = -1e30f, l_run = 0.f;
    float o[16];
    #pragma unroll
    for (int d = 0; d < 16; d++) o[d] = 0.f;

    for (int jt = 0; jt <= qt; jt++) {
        const size_t base = ((size_t)(b * Sc + jt * 64 + r)) * Dc + hh * DKc + p * 16;
        #pragma unroll
        for (int w = 0; w < 4; w++) {
            *(float4*)&Kt[r][p * 16 + w * 4] = *(const float4*)(g_K + base + w * 4);
            *(float4*)&Vt[r][p * 16 + w * 4] = *(const float4*)(g_V + base + w * 4);
        }
        __syncthreads();

        for (int j = 0; j < 64; j++) {
            float s = 0.f;
            #pragma unroll
            for (int d = 0; d < 16; d++) s += q[d] * Kt[j][p * 16 + d];
            s += __shfl_xor_sync(0xffffffffu, s, 1);
            s += __shfl_xor_sync(0xffffffffu, s, 2);
            s *= scale;
            if (jt * 64 + j < i) {
                float m_new = fmaxf(m_run, s);
                float corr  = __expf(m_run - m_new);
                float pj    = __expf(s - m_new);
                l_run = l_run * corr + pj;
                #pragma unroll
                for (int d = 0; d < 16; d++)
                    o[d] = o[d] * corr + pj * Vt[j][p * 16 + d];
                m_run = m_new;
            }
        }
        __syncthreads();
    }

    float inv = (l_run > 0.f) ? (1.f / l_run) : 0.f;
    float* op = g_O + ((size_t)(b * Sc + i)) * Dc + hh * DKc + p * 16;
    #pragma unroll
    for (int d = 0; d < 16; d++) op[d] = o[d] * inv;
}

// ---------------- fused add + LayerNorm + quantize ----------------
__global__ __launch_bounds__(256)
void add_ln_kernel(float* __restrict__ x, const float* __restrict__ resid,
                   const float* __restrict__ g, const float* __restrict__ b) {
    const int row = blockIdx.x;
    const int tid = threadIdx.x;
    const size_t base = (size_t)row * Dc;
    float v0 = x[base + tid]       + resid[base + tid];
    float v1 = x[base + tid + 256] + resid[base + tid + 256];
    float s  = v0 + v1;
    float ss = v0 * v0 + v1 * v1;

    __shared__ float sbuf[8], ssbuf[8], smax[8];
    #pragma unroll
    for (int o = 16; o > 0; o >>= 1) {
        s  += __shfl_xor_sync(0xffffffffu, s, o);
        ss += __shfl_xor_sync(0xffffffffu, ss, o);
    }
    if ((tid & 31) == 0) { sbuf[tid >> 5] = s; ssbuf[tid >> 5] = ss; }
    __syncthreads();
    if (tid < 32) {
        s  = (tid < 8) ? sbuf[tid]  : 0.f;
        ss = (tid < 8) ? ssbuf[tid] : 0.f;
        #pragma unroll
        for (int o = 4; o > 0; o >>= 1) {
            s  += __shfl_xor_sync(0xffffffffu, s, o);
            ss += __shfl_xor_sync(0xffffffffu, ss, o);
        }
        if (tid == 0) { sbuf[0] = s; ssbuf[0] = ss; }
    }
    __syncthreads();
    float mean = sbuf[0] * (1.f / 512.f);
    float var  = ssbuf[0] * (1.f / 512.f) - mean * mean;
    float rstd = rsqrtf(var + 1e-5f);
    float o0 = (v0 - mean) * rstd * g[tid]       + b[tid];
    float o1 = (v1 - mean) * rstd * g[tid + 256] + b[tid + 256];
    x[base + tid]       = o0;
    x[base + tid + 256] = o1;

    float mx = blockmax256(fmaxf(fabsf(o0), fabsf(o1)), smax, tid);
    float inv = (mx > 0.f) ? QM / mx : 0.f;
    int8_t h, l;
    q2(o0, inv, h, l); g_xqh[base + tid] = h;       g_xql[base + tid] = l;
    q2(o1, inv, h, l); g_xqh[base + tid + 256] = h; g_xql[base + tid + 256] = l;
    if (tid == 0) g_sx[row] = mx * (1.f / QM);
}

// ---------------- concat [x | qe] row-block + quantize ----------------
__global__ __launch_bounds__(256)
void concat_kernel() {
    __shared__ float sb[8];
    const int row = blockIdx.x, tid = threadIdx.x;
    const size_t xb = (size_t)row * Dc;
    const size_t cb = (size_t)row * 2 * Dc;
    float v[4];
    #pragma unroll
    for (int j = 0; j < 4; j++) {
        int c = tid + j * 256;
        v[j] = (c < Dc) ? g_x[xb + c] : g_qe[xb + c - Dc];
    }
    float m = fmaxf(fmaxf(fabsf(v[0]), fabsf(v[1])),
                    fmaxf(fabsf(v[2]), fabsf(v[3])));
    m = blockmax256(m, sb, tid);
    float inv = (m > 0.f) ? QM / m : 0.f;
    #pragma unroll
    for (int j = 0; j < 4; j++) {
        int8_t h, l;
        q2(v[j], inv, h, l);
        g_Cqh[cb + tid + j * 256] = h;
        g_Cql[cb + tid + j * 256] = l;
    }
    if (tid == 0) g_sC[row] = m * (1.f / QM);
}

// ---------------- host ----------------
static inline void prep_w(const float* W, int8_t* qh, int8_t* ql,
                          float* s, float* si, int K, int N, int Npad) {
    wcolmax_kernel<<<(Npad + 255) / 256, 256>>>(W, K, N, Npad, s, si);
    wquant_kernel<<<dim3(Npad / 32, K / 32), dim3(32, 8)>>>(W, qh, ql, si, K, N);
}
static inline void gemm_i8(const int8_t* aqh, const int8_t* aql, const float* sa,
                           const int8_t* bqh, const int8_t* bql, const float* sb,
                           const float* bias, float* C, int K, int N, int Npad,
                           int relu) {
    gemm_i8_kernel<<<dim3(Npad / 128, Mr / 128), 256, GEMM_DSMEM>>>(
        aqh, aql, sa, bqh, bql, sb, bias, C, K, N, relu);
}

extern "C" void kernel_launch(void* const* d_in, const int* in_sizes, int n_in,
                              void* d_out, int out_size) {
    const int*   q_data = (const int*)d_in[0];
    const int*   target = (const int*)d_in[1];
    const float* pe     = (const float*)d_in[2];
    const float* q_emb  = (const float*)d_in[3];
    const float* qa_emb = (const float*)d_in[4];
    const float* Wk     = (const float*)d_in[5];
    const float* bk     = (const float*)d_in[6];
    const float* Wv     = (const float*)d_in[7];
    const float* bv     = (const float*)d_in[8];
    const float* Wo     = (const float*)d_in[9];
    const float* bo     = (const float*)d_in[10];
    const float* ln1_g  = (const float*)d_in[11];
    const float* ln1_b  = (const float*)d_in[12];
    const float* W1     = (const float*)d_in[13];
    const float* b1     = (const float*)d_in[14];
    const float* W2     = (const float*)d_in[15];
    const float* b2     = (const float*)d_in[16];
    const float* ln2_g  = (const float*)d_in[17];
    const float* ln2_b  = (const float*)d_in[18];
    const float* Wout1  = (const float*)d_in[19];
    const float* bout1  = (const float*)d_in[20];
    const float* Wout2  = (const float*)d_in[21];
    const float* bout2  = (const float*)d_in[22];
    const float* Wout3  = (const float*)d_in[23];
    const float* bout3  = (const float*)d_in[24];
    float* out = (float*)d_out;

    cudaFuncSetAttribute(gemm_i8_kernel,
                         cudaFuncAttributeMaxDynamicSharedMemorySize, GEMM_DSMEM);

    float *p_x, *p_K, *p_V, *p_P, *p_O, *p_F1f, *p_H1f, *p_H2f;
    cudaGetSymbolAddress((void**)&p_x,   g_x);
    cudaGetSymbolAddress((void**)&p_K,   g_K);
    cudaGetSymbolAddress((void**)&p_V,   g_V);
    cudaGetSymbolAddress((void**)&p_P,   g_P);
    cudaGetSymbolAddress((void**)&p_O,   g_O);
    cudaGetSymbolAddress((void**)&p_F1f, g_F1f);
    cudaGetSymbolAddress((void**)&p_H1f, g_H1f);
    cudaGetSymbolAddress((void**)&p_H2f, g_H2f);

    int8_t *xqh, *xql, *yqh, *yql, *Oqh, *Oql, *F1qh, *F1ql, *Cqh, *Cql,
           *H1qh, *H1ql, *H2qh, *H2ql;
    float *sx, *sy, *sO, *sF1, *sC, *sH1, *sH2;
    cudaGetSymbolAddress((void**)&xqh, g_xqh);   cudaGetSymbolAddress((void**)&xql, g_xql);
    cudaGetSymbolAddress((void**)&yqh, g_yqh);   cudaGetSymbolAddress((void**)&yql, g_yql);
    cudaGetSymbolAddress((void**)&Oqh, g_Oqh);   cudaGetSymbolAddress((void**)&Oql, g_Oql);
    cudaGetSymbolAddress((void**)&F1qh, g_F1qh); cudaGetSymbolAddress((void**)&F1ql, g_F1ql);
    cudaGetSymbolAddress((void**)&Cqh, g_Cqh);   cudaGetSymbolAddress((void**)&Cql, g_Cql);
    cudaGetSymbolAddress((void**)&H1qh, g_H1qh); cudaGetSymbolAddress((void**)&H1ql, g_H1ql);
    cudaGetSymbolAddress((void**)&H2qh, g_H2qh); cudaGetSymbolAddress((void**)&H2ql, g_H2ql);
    cudaGetSymbolAddress((void**)&sx, g_sx);   cudaGetSymbolAddress((void**)&sy, g_sy);
    cudaGetSymbolAddress((void**)&sO, g_sOr);  cudaGetSymbolAddress((void**)&sF1, g_sF1);
    cudaGetSymbolAddress((void**)&sC, g_sC);   cudaGetSymbolAddress((void**)&sH1, g_sH1);
    cudaGetSymbolAddress((void**)&sH2, g_sH2);

    int8_t *wkh, *wkl, *wvh, *wvl, *woh, *wol, *w1h, *w1l, *w2h, *w2l;
    int8_t *wo1h, *wo1l, *wo2h, *wo2l, *wo3h, *wo3l;
    float *sW, *iW;
    cudaGetSymbolAddress((void**)&wkh, g_Wk_h);  cudaGetSymbolAddress((void**)&wkl, g_Wk_l);
    cudaGetSymbolAddress((void**)&wvh, g_Wv_h);  cudaGetSymbolAddress((void**)&wvl, g_Wv_l);
    cudaGetSymbolAddress((void**)&woh, g_Wo_h);  cudaGetSymbolAddress((void**)&wol, g_Wo_l);
    cudaGetSymbolAddress((void**)&w1h, g_W1_h);  cudaGetSymbolAddress((void**)&w1l, g_W1_l);
    cudaGetSymbolAddress((void**)&w2h, g_W2_h);  cudaGetSymbolAddress((void**)&w2l, g_W2_l);
    cudaGetSymbolAddress((void**)&wo1h, g_Wo1_h); cudaGetSymbolAddress((void**)&wo1l, g_Wo1_l);
    cudaGetSymbolAddress((void**)&wo2h, g_Wo2_h); cudaGetSymbolAddress((void**)&wo2l, g_Wo2_l);
    cudaGetSymbolAddress((void**)&wo3h, g_Wo3_h); cudaGetSymbolAddress((void**)&wo3l, g_Wo3_l);
    cudaGetSymbolAddress((void**)&sW, g_sW);
    cudaGetSymbolAddress((void**)&iW, g_iW);

    // weight prep
    for (int l = 0; l < Lc; l++) {
        size_t oDD = (size_t)l * Dc * Dc;
        size_t oDF = (size_t)l * Dc * DFFc;
        prep_w(Wk + oDD, wkh + oDD, wkl + oDD, sW + OFF_WK + l * Dc,
               iW + OFF_WK + l * Dc, Dc, Dc, Dc);
        prep_w(Wv + oDD, wvh + oDD, wvl + oDD, sW + OFF_WV + l * Dc,
               iW + OFF_WV + l * Dc, Dc, Dc, Dc);
        prep_w(Wo + oDD, woh + oDD, wol + oDD, sW + OFF_WO + l * Dc,
               iW + OFF_WO + l * Dc, Dc, Dc, Dc);
        prep_w(W1 + oDF, w1h + oDF, w1l + oDF, sW + OFF_W1 + l * DFFc,
               iW + OFF_W1 + l * DFFc, Dc, DFFc, DFFc);
        prep_w(W2 + oDF, w2h + oDF, w2l + oDF, sW + OFF_W2 + l * Dc,
               iW + OFF_W2 + l * Dc, DFFc, Dc, Dc);
    }
    prep_w(Wout1, wo1h, wo1l, sW + OFF_WO1, iW + OFF_WO1, 2 * Dc, FC1c, FC1c);
    prep_w(Wout2, wo2h, wo2l, sW + OFF_WO2, iW + OFF_WO2, FC1c, FC2c, FC2c);
    prep_w(Wout3, wo3h, wo3l, sW + OFF_WO3, iW + OFF_WO3, FC2c, NSKc, NSKp);

    // embed
    embed_kernel<<<Mr, 256>>>(q_data, target, pe, q_emb, qa_emb);

    // transformer layers
    for (int l = 0; l < Lc; l++) {
        size_t oDD = (size_t)l * Dc * Dc;
        size_t oDF = (size_t)l * Dc * DFFc;
        gemm_i8(xqh, xql, sx, wkh + oDD, wkl + oDD, sW + OFF_WK + l * Dc,
                bk + l * Dc, p_K, Dc, Dc, Dc, 0);
        gemm_i8(yqh, yql, sy, wvh + oDD, wvl + oDD, sW + OFF_WV + l * Dc,
                bv + l * Dc, p_V, Dc, Dc, Dc, 0);
        attn_kernel<<<dim3(Sc / 64, Hc, Bc), 256>>>();
        rowquant_kernel<<<Mr, 256>>>(p_O, Oqh, Oql, sO, Dc);
        gemm_i8(Oqh, Oql, sO, woh + oDD, wol + oDD, sW + OFF_WO + l * Dc,
                bo + l * Dc, p_P, Dc, Dc, Dc, 0);
        add_ln_kernel<<<Mr, 256>>>(p_x, p_P, ln1_g + l * Dc, ln1_b + l * Dc);
        gemm_i8(xqh, xql, sx, w1h + oDF, w1l + oDF, sW + OFF_W1 + l * DFFc,
                b1 + l * DFFc, p_F1f, Dc, DFFc, DFFc, 1);
        rowquant_kernel<<<Mr, 256>>>(p_F1f, F1qh, F1ql, sF1, DFFc);
        gemm_i8(F1qh, F1ql, sF1, w2h + oDF, w2l + oDF, sW + OFF_W2 + l * Dc,
                b2 + l * Dc, p_P, DFFc, Dc, Dc, 0);
        add_ln_kernel<<<Mr, 256>>>(p_x, p_P, ln2_g + l * Dc, ln2_b + l * Dc);
    }

    // head
    concat_kernel<<<Mr, 256>>>();
    gemm_i8(Cqh, Cql, sC, wo1h, wo1l, sW + OFF_WO1, bout1, p_H1f,
            2 * Dc, FC1c, FC1c, 1);
    rowquant_kernel<<<Mr, 256>>>(p_H1f, H1qh, H1ql, sH1, FC1c);
    gemm_i8(H1qh, H1ql, sH1, wo2h, wo2l, sW + OFF_WO2, bout2, p_H2f,
            FC1c, FC2c, FC2c, 1);
    rowquant_kernel<<<Mr, 256>>>(p_H2f, H2qh, H2ql, sH2, FC2c);
    gemm_i8(H2qh, H2ql, sH2, wo3h, wo3l, sW + OFF_WO3, bout3, out,
            FC2c, NSKc, NSKp, 0);
}

// round 8
// speedup vs baseline: 1.5514x; 1.5514x over previous
#include <cuda_runtime.h>
#include <cuda_fp16.h>
#include <math.h>
#include <stdint.h>

#define Bc   64
#define Sc   512
#define Dc   512
#define Hc   8
#define DKc  64
#define Lc   4
#define DFFc 2048
#define NSKc 300
#define NSKp 384
#define FC1c 512
#define FC2c 256
#define Mr   (Bc * Sc)

// ---------------- fp32 scratch ----------------
__device__ float g_qe[(size_t)Mr * Dc];
__device__ float g_x [(size_t)Mr * Dc];
__device__ float g_K [(size_t)Mr * Dc];
__device__ float g_V [(size_t)Mr * Dc];
__device__ float g_P [(size_t)Mr * Dc];

// ---------------- fp16 hi/lo activation pairs ----------------
__device__ __half g_xh [(size_t)Mr * Dc],   g_xl [(size_t)Mr * Dc];
__device__ __half g_yh [(size_t)Mr * Dc],   g_yl [(size_t)Mr * Dc];
__device__ __half g_Oh [(size_t)Mr * Dc],   g_Ol [(size_t)Mr * Dc];
__device__ __half g_F1h[(size_t)Mr * DFFc], g_F1l[(size_t)Mr * DFFc];
__device__ __half g_Ch [(size_t)Mr * 2*Dc], g_Cl [(size_t)Mr * 2*Dc];
__device__ __half g_H1h[(size_t)Mr * FC1c], g_H1l[(size_t)Mr * FC1c];
__device__ __half g_H2h[(size_t)Mr * FC2c], g_H2l[(size_t)Mr * FC2c];

// ---------------- fp16 hi/lo weights (transposed [N][K]) ----------------
__device__ __half g_Wk_h[(size_t)Lc * Dc * Dc],   g_Wk_l[(size_t)Lc * Dc * Dc];
__device__ __half g_Wv_h[(size_t)Lc * Dc * Dc],   g_Wv_l[(size_t)Lc * Dc * Dc];
__device__ __half g_Wo_h[(size_t)Lc * Dc * Dc],   g_Wo_l[(size_t)Lc * Dc * Dc];
__device__ __half g_W1_h[(size_t)Lc * Dc * DFFc], g_W1_l[(size_t)Lc * Dc * DFFc];
__device__ __half g_W2_h[(size_t)Lc * DFFc * Dc], g_W2_l[(size_t)Lc * DFFc * Dc];
__device__ __half g_Wo1_h[(size_t)2 * Dc * FC1c], g_Wo1_l[(size_t)2 * Dc * FC1c];
__device__ __half g_Wo2_h[(size_t)FC1c * FC2c],   g_Wo2_l[(size_t)FC1c * FC2c];
__device__ __half g_Wo3_h[(size_t)NSKp * FC2c],   g_Wo3_l[(size_t)NSKp * FC2c];

// ---------------- helpers ----------------
__device__ __forceinline__ uint32_t smem_u32(const void* p) {
    uint32_t a;
    asm("{ .reg .u64 t; cvta.to.shared.u64 t, %1; cvt.u32.u64 %0, t; }"
        : "=r"(a) : "l"(p));
    return a;
}
__device__ __forceinline__ void split2(float v, __half& h, __half& l) {
    h = __float2half_rn(v);
    l = __float2half_rn(v - __half2float(h));
}

#define CPA16(dst, src)                                                       \
    asm volatile("cp.async.cg.shared.global [%0], [%1], 16;"                  \
                 :: "r"(dst), "l"(src) : "memory")

#define LDMX4(R, addr)                                                        \
    asm volatile("ldmatrix.sync.aligned.m8n8.x4.shared.b16 {%0,%1,%2,%3}, [%4];" \
        : "=r"((R)[0]), "=r"((R)[1]), "=r"((R)[2]), "=r"((R)[3]) : "r"(addr))

#define LDMX2(R, addr)                                                        \
    asm volatile("ldmatrix.sync.aligned.m8n8.x2.shared.b16 {%0,%1}, [%2];"    \
        : "=r"((R)[0]), "=r"((R)[1]) : "r"(addr))

// fp32-accumulator MMA (main term)
#define MMA16816(d, a, b)                                                     \
    asm volatile("mma.sync.aligned.m16n8k16.row.col.f32.f16.f16.f32 "         \
        "{%0,%1,%2,%3}, {%4,%5,%6,%7}, {%8,%9}, {%0,%1,%2,%3};"               \
        : "+f"((d)[0]), "+f"((d)[1]), "+f"((d)[2]), "+f"((d)[3])              \
        : "r"((a)[0]), "r"((a)[1]), "r"((a)[2]), "r"((a)[3]),                 \
          "r"((b)[0]), "r"((b)[1]))

// fp16-accumulator MMA (correction terms — magnitude ~2^-11 of main)
#define MMA16816H(d, a, b)                                                    \
    asm volatile("mma.sync.aligned.m16n8k16.row.col.f16.f16.f16.f16 "         \
        "{%0,%1}, {%2,%3,%4,%5}, {%6,%7}, {%0,%1};"                           \
        : "+r"((d)[0]), "+r"((d)[1])                                          \
        : "r"((a)[0]), "r"((a)[1]), "r"((a)[2]), "r"((a)[3]),                 \
          "r"((b)[0]), "r"((b)[1]))

// ---------------- weight prep: transpose + hi/lo split ----------------
__global__ void split_w_kernel(const float* __restrict__ W,
                               __half* __restrict__ Oh, __half* __restrict__ Ol,
                               int K, int N) {
    __shared__ float t[32][33];
    int k0 = blockIdx.y * 32, n0 = blockIdx.x * 32;
    #pragma unroll
    for (int i = 0; i < 4; i++) {
        int k = k0 + threadIdx.y + i * 8;
        int n = n0 + threadIdx.x;
        t[threadIdx.y + i * 8][threadIdx.x] = (n < N) ? W[(size_t)k * N + n] : 0.f;
    }
    __syncthreads();
    #pragma unroll
    for (int i = 0; i < 4; i++) {
        int n = n0 + threadIdx.y + i * 8;
        int k = k0 + threadIdx.x;
        float v = t[threadIdx.x][threadIdx.y + i * 8];
        __half h, l; split2(v, h, l);
        Oh[(size_t)n * K + k] = h;
        Ol[(size_t)n * K + k] = l;
    }
}

// ---------------- split-fp16 mma.sync GEMM ----------------
#define APITCH 40
#define TILE_B (128 * APITCH * 2)    // 10240
#define STAGE_B (4 * TILE_B)         // 40960
#define GEMM_DSMEM (2 * STAGE_B)     // 81920

__device__ __forceinline__ void issue_stage(
    uint32_t sb, const __half* Ah_g, const __half* Al_g,
    const __half* Bh_g, const __half* Bl_g,
    int m0, int n0, int K, int kk, int tid) {
    #pragma unroll
    for (int p = 0; p < 2; p++) {
        int c = p * 256 + tid;
        int row = c >> 2, q = c & 3;
        uint32_t d = sb + (uint32_t)(row * 80 + q * 16);
        size_t ao = (size_t)(m0 + row) * K + kk + q * 8;
        size_t bo = (size_t)(n0 + row) * K + kk + q * 8;
        CPA16(d,              Ah_g + ao);
        CPA16(d + TILE_B,     Al_g + ao);
        CPA16(d + 2 * TILE_B, Bh_g + bo);
        CPA16(d + 3 * TILE_B, Bl_g + bo);
    }
    asm volatile("cp.async.commit_group;" ::: "memory");
}

__global__ __launch_bounds__(256, 1)
void gemm_mma_kernel(const __half* __restrict__ Ah_g,
                     const __half* __restrict__ Al_g,
                     const __half* __restrict__ Bh_g,
                     const __half* __restrict__ Bl_g,
                     const float* __restrict__ bias,
                     float* __restrict__ Cf,
                     __half* __restrict__ Coh, __half* __restrict__ Col,
                     int K, int N, int relu) {
    extern __shared__ char smem[];
    const int tid  = threadIdx.x;
    const int wid  = tid >> 5;
    const int lane = tid & 31;
    const int m0 = blockIdx.y * 128;
    const int n0 = blockIdx.x * 128;
    const int warp_m = (wid >> 2) * 64;
    const int warp_n = (wid & 3) * 32;

    const uint32_t sbase = smem_u32(smem);

    float acc[4][4][4];         // fp32 main accumulators
    uint32_t accc[4][4][2];     // fp16x2 correction accumulators
    #pragma unroll
    for (int i = 0; i < 4; i++)
        #pragma unroll
        for (int j = 0; j < 4; j++) {
            #pragma unroll
            for (int e = 0; e < 4; e++) acc[i][j][e] = 0.f;
            accc[i][j][0] = 0u; accc[i][j][1] = 0u;
        }

    const int KT = K >> 5;
    const int r8  = lane & 7;
    const int sub = lane >> 3;
    const uint32_t a_lane_off =
        (uint32_t)(((warp_m + r8 + (sub & 1) * 8) * APITCH + (sub >> 1) * 8) * 2);
    const uint32_t b_lane_off =
        (uint32_t)(((warp_n + r8) * APITCH + (sub & 1) * 8) * 2);

    issue_stage(sbase, Ah_g, Al_g, Bh_g, Bl_g, m0, n0, K, 0, tid);

    for (int kt = 0; kt < KT; kt++) {
        asm volatile("cp.async.wait_group 0;" ::: "memory");
        __syncthreads();
        if (kt + 1 < KT)
            issue_stage(sbase + ((kt + 1) & 1) * STAGE_B, Ah_g, Al_g, Bh_g, Bl_g,
                        m0, n0, K, (kt + 1) << 5, tid);

        const uint32_t stoff = (kt & 1) * STAGE_B;
        const uint32_t abase = sbase + stoff + a_lane_off;
        const uint32_t bbase = sbase + stoff + 2 * TILE_B + b_lane_off;

        #pragma unroll
        for (int ks = 0; ks < 2; ks++) {
            const uint32_t ak = abase + ks * 32;
            const uint32_t bk = bbase + ks * 32;

            uint32_t Ahf[4][4], Bhf[4][2];
            #pragma unroll
            for (int fi = 0; fi < 4; fi++)
                LDMX4(Ahf[fi], ak + fi * (16 * APITCH * 2));
            #pragma unroll
            for (int fj = 0; fj < 4; fj++)
                LDMX2(Bhf[fj], bk + fj * (8 * APITCH * 2));
            // main term: fp32 accumulate
            #pragma unroll
            for (int fi = 0; fi < 4; fi++)
                #pragma unroll
                for (int fj = 0; fj < 4; fj++)
                    MMA16816(acc[fi][fj], Ahf[fi], Bhf[fj]);

            // corrections: fp16 accumulate
            uint32_t Blf[4][2];
            #pragma unroll
            for (int fj = 0; fj < 4; fj++)
                LDMX2(Blf[fj], bk + TILE_B + fj * (8 * APITCH * 2));
            #pragma unroll
            for (int fi = 0; fi < 4; fi++)
                #pragma unroll
                for (int fj = 0; fj < 4; fj++)
                    MMA16816H(accc[fi][fj], Ahf[fi], Blf[fj]);

            uint32_t Alf[4][4];
            #pragma unroll
            for (int fi = 0; fi < 4; fi++)
                LDMX4(Alf[fi], ak + TILE_B + fi * (16 * APITCH * 2));
            #pragma unroll
            for (int fi = 0; fi < 4; fi++)
                #pragma unroll
                for (int fj = 0; fj < 4; fj++)
                    MMA16816H(accc[fi][fj], Alf[fi], Bhf[fj]);
        }
    }

    // ---- epilogue ----
    #pragma unroll
    for (int fj = 0; fj < 4; fj++) {
        const int c0 = n0 + warp_n + fj * 8 + 2 * (lane & 3);
        const bool c0ok = (c0 < N), c1ok = (c0 + 1 < N);
        const float b0 = c0ok ? bias[c0] : 0.f;
        const float b1 = c1ok ? bias[c0 + 1] : 0.f;
        #pragma unroll
        for (int fi = 0; fi < 4; fi++) {
            const int r0 = m0 + warp_m + fi * 16 + (lane >> 2);
            float2 cl = __half22float2(*(__half2*)&accc[fi][fj][0]);
            float2 ch = __half22float2(*(__half2*)&accc[fi][fj][1]);
            float v0 = acc[fi][fj][0] + cl.x + b0;
            float v1 = acc[fi][fj][1] + cl.y + b1;
            float v2 = acc[fi][fj][2] + ch.x + b0;
            float v3 = acc[fi][fj][3] + ch.y + b1;
            if (relu) {
                v0 = fmaxf(v0, 0.f); v1 = fmaxf(v1, 0.f);
                v2 = fmaxf(v2, 0.f); v3 = fmaxf(v3, 0.f);
            }
            if (Cf) {
                if (c0ok) {
                    Cf[(size_t)r0 * N + c0]       = v0;
                    Cf[(size_t)(r0 + 8) * N + c0] = v2;
                }
                if (c1ok) {
                    Cf[(size_t)r0 * N + c0 + 1]       = v1;
                    Cf[(size_t)(r0 + 8) * N + c0 + 1] = v3;
                }
            } else {
                __half h, l;
                if (c0ok) {
                    split2(v0, h, l);
                    Coh[(size_t)r0 * N + c0] = h; Col[(size_t)r0 * N + c0] = l;
                    split2(v2, h, l);
                    Coh[(size_t)(r0 + 8) * N + c0] = h;
                    Col[(size_t)(r0 + 8) * N + c0] = l;
                }
                if (c1ok) {
                    split2(v1, h, l);
                    Coh[(size_t)r0 * N + c0 + 1] = h;
                    Col[(size_t)r0 * N + c0 + 1] = l;
                    split2(v3, h, l);
                    Coh[(size_t)(r0 + 8) * N + c0 + 1] = h;
                    Col[(size_t)(r0 + 8) * N + c0 + 1] = l;
                }
            }
        }
    }
}

// ---------------- embed ----------------
__global__ void embed_kernel(const int* __restrict__ q_data,
                             const int* __restrict__ target,
                             const float* __restrict__ pe,
                             const float* __restrict__ q_emb,
                             const float* __restrict__ qa_emb) {
    size_t idx = (size_t)blockIdx.x * blockDim.x + threadIdx.x;
    if (idx >= (size_t)Mr * Dc) return;
    int bs = (int)(idx / Dc);
    int d  = (int)(idx % Dc);
    int s  = bs % Sc;
    float qe = q_emb[(size_t)q_data[bs] * Dc + d];
    float p  = pe[(size_t)s * Dc + d];
    float x  = qe + p;
    float y  = qa_emb[(size_t)target[bs] * Dc + d] + qe + p;
    g_qe[idx] = qe;
    g_x [idx] = x;
    __half h, l;
    split2(x, h, l); g_xh[idx] = h; g_xl[idx] = l;
    split2(y, h, l); g_yh[idx] = h; g_yl[idx] = l;
}

// ---------------- flash attention (fp32 in, fp16-pair out) ----------------
__global__ __launch_bounds__(256)
void attn_kernel() {
    const int qt = blockIdx.x, hh = blockIdx.y, b = blockIdx.z;
    const int tid = threadIdx.x;
    const int r = tid >> 2;
    const int p = tid & 3;
    const int i = qt * 64 + r;
    const float scale = 0.125f;

    __shared__ float Kt[64][64];
    __shared__ float Vt[64][64];

    float q[16];
    {
        const float* qp = g_K + ((size_t)(b * Sc + i)) * Dc + hh * DKc + p * 16;
        #pragma unroll
        for (int w = 0; w < 4; w++) {
            float4 v = *(const float4*)(qp + w * 4);
            q[w * 4 + 0] = v.x; q[w * 4 + 1] = v.y;
            q[w * 4 + 2] = v.z; q[w * 4 + 3] = v.w;
        }
    }

    float m_run = -1e30f, l_run = 0.f;
    float o[16];
    #pragma unroll
    for (int d = 0; d < 16; d++) o[d] = 0.f;

    for (int jt = 0; jt <= qt; jt++) {
        const size_t base = ((size_t)(b * Sc + jt * 64 + r)) * Dc + hh * DKc + p * 16;
        #pragma unroll
        for (int w = 0; w < 4; w++) {
            *(float4*)&Kt[r][p * 16 + w * 4] = *(const float4*)(g_K + base + w * 4);
            *(float4*)&Vt[r][p * 16 + w * 4] = *(const float4*)(g_V + base + w * 4);
        }
        __syncthreads();

        for (int j = 0; j < 64; j++) {
            float s = 0.f;
            #pragma unroll
            for (int d = 0; d < 16; d++) s += q[d] * Kt[j][p * 16 + d];
            s += __shfl_xor_sync(0xffffffffu, s, 1);
            s += __shfl_xor_sync(0xffffffffu, s, 2);
            s *= scale;
            if (jt * 64 + j < i) {
                float m_new = fmaxf(m_run, s);
                float corr  = __expf(m_run - m_new);
                float pj    = __expf(s - m_new);
                l_run = l_run * corr + pj;
                #pragma unroll
                for (int d = 0; d < 16; d++)
                    o[d] = o[d] * corr + pj * Vt[j][p * 16 + d];
                m_run = m_new;
            }
        }
        __syncthreads();
    }

    float inv = (l_run > 0.f) ? (1.f / l_run) : 0.f;
    size_t ob = ((size_t)(b * Sc + i)) * Dc + hh * DKc + p * 16;
    #pragma unroll
    for (int d = 0; d < 16; d++) {
        __half h, l;
        split2(o[d] * inv, h, l);
        g_Oh[ob + d] = h;
        g_Ol[ob + d] = l;
    }
}

// ---------------- fused add + LayerNorm (+ fp16 split out) ----------------
__global__ __launch_bounds__(256)
void add_ln_kernel(float* __restrict__ x, const float* __restrict__ resid,
                   const float* __restrict__ g, const float* __restrict__ b) {
    const int row = blockIdx.x;
    const int tid = threadIdx.x;
    const size_t base = (size_t)row * Dc;
    float v0 = x[base + tid]       + resid[base + tid];
    float v1 = x[base + tid + 256] + resid[base + tid + 256];
    float s  = v0 + v1;
    float ss = v0 * v0 + v1 * v1;

    __shared__ float sbuf[8], ssbuf[8];
    #pragma unroll
    for (int o = 16; o > 0; o >>= 1) {
        s  += __shfl_xor_sync(0xffffffffu, s, o);
        ss += __shfl_xor_sync(0xffffffffu, ss, o);
    }
    if ((tid & 31) == 0) { sbuf[tid >> 5] = s; ssbuf[tid >> 5] = ss; }
    __syncthreads();
    if (tid < 32) {
        s  = (tid < 8) ? sbuf[tid]  : 0.f;
        ss = (tid < 8) ? ssbuf[tid] : 0.f;
        #pragma unroll
        for (int o = 4; o > 0; o >>= 1) {
            s  += __shfl_xor_sync(0xffffffffu, s, o);
            ss += __shfl_xor_sync(0xffffffffu, ss, o);
        }
        if (tid == 0) { sbuf[0] = s; ssbuf[0] = ss; }
    }
    __syncthreads();
    float mean = sbuf[0] * (1.f / 512.f);
    float var  = ssbuf[0] * (1.f / 512.f) - mean * mean;
    float rstd = rsqrtf(var + 1e-5f);
    float o0 = (v0 - mean) * rstd * g[tid]       + b[tid];
    float o1 = (v1 - mean) * rstd * g[tid + 256] + b[tid + 256];
    x[base + tid]       = o0;
    x[base + tid + 256] = o1;
    __half h, l;
    split2(o0, h, l); g_xh[base + tid] = h;       g_xl[base + tid] = l;
    split2(o1, h, l); g_xh[base + tid + 256] = h; g_xl[base + tid + 256] = l;
}

// ---------------- concat [x | qe] -> fp16 pair ----------------
__global__ void concat_kernel() {
    size_t idx = (size_t)blockIdx.x * blockDim.x + threadIdx.x;
    if (idx >= (size_t)Mr * 2 * Dc) return;
    int bs = (int)(idx / (2 * Dc));
    int c  = (int)(idx % (2 * Dc));
    float v = (c < Dc) ? g_x[(size_t)bs * Dc + c]
                       : g_qe[(size_t)bs * Dc + (c - Dc)];
    __half h, l;
    split2(v, h, l);
    g_Ch[idx] = h;
    g_Cl[idx] = l;
}

// ---------------- host ----------------
static inline void split_w(const float* W, __half* oh, __half* ol,
                           int K, int N, int Npad) {
    split_w_kernel<<<dim3(Npad / 32, K / 32), dim3(32, 8)>>>(W, oh, ol, K, N);
}
static inline void gemmF32(const __half* ah, const __half* al,
                           const __half* bh, const __half* bl,
                           const float* bias, float* C, int K, int N, int Npad,
                           int relu) {
    gemm_mma_kernel<<<dim3(Npad / 128, Mr / 128), 256, GEMM_DSMEM>>>(
        ah, al, bh, bl, bias, C, nullptr, nullptr, K, N, relu);
}
static inline void gemmF16(const __half* ah, const __half* al,
                           const __half* bh, const __half* bl,
                           const float* bias, __half* oh, __half* ol,
                           int K, int N, int Npad, int relu) {
    gemm_mma_kernel<<<dim3(Npad / 128, Mr / 128), 256, GEMM_DSMEM>>>(
        ah, al, bh, bl, bias, nullptr, oh, ol, K, N, relu);
}

extern "C" void kernel_launch(void* const* d_in, const int* in_sizes, int n_in,
                              void* d_out, int out_size) {
    const int*   q_data = (const int*)d_in[0];
    const int*   target = (const int*)d_in[1];
    const float* pe     = (const float*)d_in[2];
    const float* q_emb  = (const float*)d_in[3];
    const float* qa_emb = (const float*)d_in[4];
    const float* Wk     = (const float*)d_in[5];
    const float* bk     = (const float*)d_in[6];
    const float* Wv     = (const float*)d_in[7];
    const float* bv     = (const float*)d_in[8];
    const float* Wo     = (const float*)d_in[9];
    const float* bo     = (const float*)d_in[10];
    const float* ln1_g  = (const float*)d_in[11];
    const float* ln1_b  = (const float*)d_in[12];
    const float* W1     = (const float*)d_in[13];
    const float* b1     = (const float*)d_in[14];
    const float* W2     = (const float*)d_in[15];
    const float* b2     = (const float*)d_in[16];
    const float* ln2_g  = (const float*)d_in[17];
    const float* ln2_b  = (const float*)d_in[18];
    const float* Wout1  = (const float*)d_in[19];
    const float* bout1  = (const float*)d_in[20];
    const float* Wout2  = (const float*)d_in[21];
    const float* bout2  = (const float*)d_in[22];
    const float* Wout3  = (const float*)d_in[23];
    const float* bout3  = (const float*)d_in[24];
    float* out = (float*)d_out;

    cudaFuncSetAttribute(gemm_mma_kernel,
                         cudaFuncAttributeMaxDynamicSharedMemorySize, GEMM_DSMEM);

    float *p_x, *p_K, *p_V, *p_P;
    cudaGetSymbolAddress((void**)&p_x, g_x);
    cudaGetSymbolAddress((void**)&p_K, g_K);
    cudaGetSymbolAddress((void**)&p_V, g_V);
    cudaGetSymbolAddress((void**)&p_P, g_P);

    __half *xh, *xl, *yh, *yl, *oh, *ol, *f1h, *f1l, *ch, *cl, *h1h, *h1l, *h2h, *h2l;
    cudaGetSymbolAddress((void**)&xh, g_xh);   cudaGetSymbolAddress((void**)&xl, g_xl);
    cudaGetSymbolAddress((void**)&yh, g_yh);   cudaGetSymbolAddress((void**)&yl, g_yl);
    cudaGetSymbolAddress((void**)&oh, g_Oh);   cudaGetSymbolAddress((void**)&ol, g_Ol);
    cudaGetSymbolAddress((void**)&f1h, g_F1h); cudaGetSymbolAddress((void**)&f1l, g_F1l);
    cudaGetSymbolAddress((void**)&ch, g_Ch);   cudaGetSymbolAddress((void**)&cl, g_Cl);
    cudaGetSymbolAddress((void**)&h1h, g_H1h); cudaGetSymbolAddress((void**)&h1l, g_H1l);
    cudaGetSymbolAddress((void**)&h2h, g_H2h); cudaGetSymbolAddress((void**)&h2l, g_H2l);

    __half *wk_h, *wk_l, *wv_h, *wv_l, *wo_h, *wo_l, *w1_h, *w1_l, *w2_h, *w2_l;
    __half *wo1_h, *wo1_l, *wo2_h, *wo2_l, *wo3_h, *wo3_l;
    cudaGetSymbolAddress((void**)&wk_h, g_Wk_h); cudaGetSymbolAddress((void**)&wk_l, g_Wk_l);
    cudaGetSymbolAddress((void**)&wv_h, g_Wv_h); cudaGetSymbolAddress((void**)&wv_l, g_Wv_l);
    cudaGetSymbolAddress((void**)&wo_h, g_Wo_h); cudaGetSymbolAddress((void**)&wo_l, g_Wo_l);
    cudaGetSymbolAddress((void**)&w1_h, g_W1_h); cudaGetSymbolAddress((void**)&w1_l, g_W1_l);
    cudaGetSymbolAddress((void**)&w2_h, g_W2_h); cudaGetSymbolAddress((void**)&w2_l, g_W2_l);
    cudaGetSymbolAddress((void**)&wo1_h, g_Wo1_h); cudaGetSymbolAddress((void**)&wo1_l, g_Wo1_l);
    cudaGetSymbolAddress((void**)&wo2_h, g_Wo2_h); cudaGetSymbolAddress((void**)&wo2_l, g_Wo2_l);
    cudaGetSymbolAddress((void**)&wo3_h, g_Wo3_h); cudaGetSymbolAddress((void**)&wo3_l, g_Wo3_l);

    // ---- launch order arranged so launch #6 (ncu -s 5 -c 1) is the GEMM ----
    {
        size_t tot = (size_t)Mr * Dc;
        embed_kernel<<<(unsigned)((tot + 255) / 256), 256>>>(q_data, target, pe,
                                                             q_emb, qa_emb);   // 1
    }
    split_w(Wk, wk_h, wk_l, Dc, Dc, Dc);                                       // 2
    split_w(Wv, wv_h, wv_l, Dc, Dc, Dc);                                       // 3
    split_w(Wo, wo_h, wo_l, Dc, Dc, Dc);                                       // 4
    split_w(W1, w1_h, w1_l, Dc, DFFc, DFFc);                                   // 5
    gemmF32(xh, xl, wk_h, wk_l, bk, p_K, Dc, Dc, Dc, 0);                       // 6 <- profiled
    split_w(W2, w2_h, w2_l, DFFc, Dc, Dc);                                     // 7

    // remaining weight prep (layers 1..3 + head)
    for (int l = 1; l < Lc; l++) {
        size_t oDD = (size_t)l * Dc * Dc;
        size_t oDF = (size_t)l * Dc * DFFc;
        split_w(Wk + oDD, wk_h + oDD, wk_l + oDD, Dc, Dc, Dc);
        split_w(Wv + oDD, wv_h + oDD, wv_l + oDD, Dc, Dc, Dc);
        split_w(Wo + oDD, wo_h + oDD, wo_l + oDD, Dc, Dc, Dc);
        split_w(W1 + oDF, w1_h + oDF, w1_l + oDF, Dc, DFFc, DFFc);
        split_w(W2 + oDF, w2_h + oDF, w2_l + oDF, DFFc, Dc, Dc);
    }
    split_w(Wout1, wo1_h, wo1_l, 2 * Dc, FC1c, FC1c);
    split_w(Wout2, wo2_h, wo2_l, FC1c, FC2c, FC2c);
    split_w(Wout3, wo3_h, wo3_l, FC2c, NSKc, NSKp);

    // transformer layers (layer 0's K-proj already launched above)
    for (int l = 0; l < Lc; l++) {
        size_t oDD = (size_t)l * Dc * Dc;
        size_t oDF = (size_t)l * Dc * DFFc;
        if (l > 0)
            gemmF32(xh, xl, wk_h + oDD, wk_l + oDD, bk + l * Dc, p_K, Dc, Dc, Dc, 0);
        gemmF32(yh, yl, wv_h + oDD, wv_l + oDD, bv + l * Dc, p_V, Dc, Dc, Dc, 0);
        attn_kernel<<<dim3(Sc / 64, Hc, Bc), 256>>>();
        gemmF32(oh, ol, wo_h + oDD, wo_l + oDD, bo + l * Dc, p_P, Dc, Dc, Dc, 0);
        add_ln_kernel<<<Mr, 256>>>(p_x, p_P, ln1_g + l * Dc, ln1_b + l * Dc);
        gemmF16(xh, xl, w1_h + oDF, w1_l + oDF, b1 + l * DFFc, f1h, f1l,
                Dc, DFFc, DFFc, 1);
        gemmF32(f1h, f1l, w2_h + oDF, w2_l + oDF, b2 + l * Dc, p_P, DFFc, Dc, Dc, 0);
        add_ln_kernel<<<Mr, 256>>>(p_x, p_P, ln2_g + l * Dc, ln2_b + l * Dc);
    }

    // head
    {
        size_t tot = (size_t)Mr * 2 * Dc;
        concat_kernel<<<(unsigned)((tot + 255) / 256), 256>>>();
    }
    gemmF16(ch, cl, wo1_h, wo1_l, bout1, h1h, h1l, 2 * Dc, FC1c, FC1c, 1);
    gemmF16(h1h, h1l, wo2_h, wo2_l, bout2, h2h, h2l, FC1c, FC2c, FC2c, 1);
    gemmF32(h2h, h2l, wo3_h, wo3_l, bout3, out, FC2c, NSKc, NSKp, 0);
}

// round 9
// speedup vs baseline: 1.9463x; 1.2546x over previous
#include <cuda_runtime.h>
#include <cuda_fp16.h>
#include <math.h>
#include <stdint.h>

#define Bc   64
#define Sc   512
#define Dc   512
#define Hc   8
#define DKc  64
#define Lc   4
#define DFFc 2048
#define NSKc 300
#define NSKp 384
#define FC1c 512
#define FC2c 256
#define Mr   (Bc * Sc)

// ---------------- fp32 scratch ----------------
__device__ float g_qe[(size_t)Mr * Dc];
__device__ float g_x [(size_t)Mr * Dc];
__device__ float g_K [(size_t)Mr * Dc];
__device__ float g_V [(size_t)Mr * Dc];
__device__ float g_P [(size_t)Mr * Dc];

// ---------------- fp16 activations (hi only) ----------------
__device__ __half g_xh [(size_t)Mr * Dc];
__device__ __half g_yh [(size_t)Mr * Dc];
__device__ __half g_Oh [(size_t)Mr * Dc];
__device__ __half g_F1h[(size_t)Mr * DFFc];
__device__ __half g_Ch [(size_t)Mr * 2 * Dc];
__device__ __half g_H1h[(size_t)Mr * FC1c];
__device__ __half g_H2h[(size_t)Mr * FC2c];

// ---------------- fp16 hi/lo weights (transposed [N][K]) ----------------
__device__ __half g_Wk_h[(size_t)Lc * Dc * Dc],   g_Wk_l[(size_t)Lc * Dc * Dc];
__device__ __half g_Wv_h[(size_t)Lc * Dc * Dc],   g_Wv_l[(size_t)Lc * Dc * Dc];
__device__ __half g_Wo_h[(size_t)Lc * Dc * Dc],   g_Wo_l[(size_t)Lc * Dc * Dc];
__device__ __half g_W1_h[(size_t)Lc * Dc * DFFc], g_W1_l[(size_t)Lc * Dc * DFFc];
__device__ __half g_W2_h[(size_t)Lc * DFFc * Dc], g_W2_l[(size_t)Lc * DFFc * Dc];
__device__ __half g_Wo1_h[(size_t)2 * Dc * FC1c], g_Wo1_l[(size_t)2 * Dc * FC1c];
__device__ __half g_Wo2_h[(size_t)FC1c * FC2c],   g_Wo2_l[(size_t)FC1c * FC2c];
__device__ __half g_Wo3_h[(size_t)NSKp * FC2c],   g_Wo3_l[(size_t)NSKp * FC2c];

// ---------------- helpers ----------------
__device__ __forceinline__ uint32_t smem_u32(const void* p) {
    uint32_t a;
    asm("{ .reg .u64 t; cvta.to.shared.u64 t, %1; cvt.u32.u64 %0, t; }"
        : "=r"(a) : "l"(p));
    return a;
}
__device__ __forceinline__ void split2(float v, __half& h, __half& l) {
    h = __float2half_rn(v);
    l = __float2half_rn(v - __half2float(h));
}

#define CPA16(dst, src)                                                       \
    asm volatile("cp.async.cg.shared.global [%0], [%1], 16;"                  \
                 :: "r"(dst), "l"(src) : "memory")

#define LDMX4(R, addr)                                                        \
    asm volatile("ldmatrix.sync.aligned.m8n8.x4.shared.b16 {%0,%1,%2,%3}, [%4];" \
        : "=r"((R)[0]), "=r"((R)[1]), "=r"((R)[2]), "=r"((R)[3]) : "r"(addr))

#define LDMX2(R, addr)                                                        \
    asm volatile("ldmatrix.sync.aligned.m8n8.x2.shared.b16 {%0,%1}, [%2];"    \
        : "=r"((R)[0]), "=r"((R)[1]) : "r"(addr))

#define MMA16816(d, a, b)                                                     \
    asm volatile("mma.sync.aligned.m16n8k16.row.col.f32.f16.f16.f32 "         \
        "{%0,%1,%2,%3}, {%4,%5,%6,%7}, {%8,%9}, {%0,%1,%2,%3};"               \
        : "+f"((d)[0]), "+f"((d)[1]), "+f"((d)[2]), "+f"((d)[3])              \
        : "r"((a)[0]), "r"((a)[1]), "r"((a)[2]), "r"((a)[3]),                 \
          "r"((b)[0]), "r"((b)[1]))

// ---------------- weight prep: transpose + hi/lo split ----------------
__global__ void split_w_kernel(const float* __restrict__ W,
                               __half* __restrict__ Oh, __half* __restrict__ Ol,
                               int K, int N) {
    __shared__ float t[32][33];
    int k0 = blockIdx.y * 32, n0 = blockIdx.x * 32;
    #pragma unroll
    for (int i = 0; i < 4; i++) {
        int k = k0 + threadIdx.y + i * 8;
        int n = n0 + threadIdx.x;
        t[threadIdx.y + i * 8][threadIdx.x] = (n < N) ? W[(size_t)k * N + n] : 0.f;
    }
    __syncthreads();
    #pragma unroll
    for (int i = 0; i < 4; i++) {
        int n = n0 + threadIdx.y + i * 8;
        int k = k0 + threadIdx.x;
        float v = t[threadIdx.x][threadIdx.y + i * 8];
        __half h, l; split2(v, h, l);
        Oh[(size_t)n * K + k] = h;
        Ol[(size_t)n * K + k] = l;
    }
}

// ---------------- 2-term GEMM: C = Ah @ (Bh + Bl) + bias ----------------
// A fp16 [M][K] (hi only), W hi/lo fp16 [Npad][K]. CTA 128x128, BK=32,
// 8 warps (2m x 4n), 2-stage cp.async, one barrier per K-iter.
#define APITCH 40
#define TILE_B (128 * APITCH * 2)    // 10240
#define STAGE_B (3 * TILE_B)         // 30720
#define GEMM_DSMEM (2 * STAGE_B)     // 61440

__device__ __forceinline__ void issue_stage(
    uint32_t sb, const __half* Ah_g, const __half* Bh_g, const __half* Bl_g,
    int m0, int n0, int K, int kk, int tid) {
    #pragma unroll
    for (int p = 0; p < 2; p++) {
        int c = p * 256 + tid;
        int row = c >> 2, q = c & 3;
        uint32_t d = sb + (uint32_t)(row * 80 + q * 16);
        size_t ao = (size_t)(m0 + row) * K + kk + q * 8;
        size_t bo = (size_t)(n0 + row) * K + kk + q * 8;
        CPA16(d,              Ah_g + ao);
        CPA16(d + TILE_B,     Bh_g + bo);
        CPA16(d + 2 * TILE_B, Bl_g + bo);
    }
    asm volatile("cp.async.commit_group;" ::: "memory");
}

__global__ __launch_bounds__(256, 2)
void gemm_mma_kernel(const __half* __restrict__ Ah_g,
                     const __half* __restrict__ Bh_g,
                     const __half* __restrict__ Bl_g,
                     const float* __restrict__ bias,
                     float* __restrict__ Cf,
                     __half* __restrict__ Coh,
                     int K, int N, int relu) {
    extern __shared__ char smem[];
    const int tid  = threadIdx.x;
    const int wid  = tid >> 5;
    const int lane = tid & 31;
    const int m0 = blockIdx.y * 128;
    const int n0 = blockIdx.x * 128;
    const int warp_m = (wid >> 2) * 64;
    const int warp_n = (wid & 3) * 32;

    const uint32_t sbase = smem_u32(smem);

    float acc[4][4][4];
    #pragma unroll
    for (int i = 0; i < 4; i++)
        #pragma unroll
        for (int j = 0; j < 4; j++)
            #pragma unroll
            for (int e = 0; e < 4; e++) acc[i][j][e] = 0.f;

    const int KT = K >> 5;
    const int r8  = lane & 7;
    const int sub = lane >> 3;
    const uint32_t a_lane_off =
        (uint32_t)(((warp_m + r8 + (sub & 1) * 8) * APITCH + (sub >> 1) * 8) * 2);
    const uint32_t b_lane_off =
        (uint32_t)(((warp_n + r8) * APITCH + (sub & 1) * 8) * 2);

    issue_stage(sbase, Ah_g, Bh_g, Bl_g, m0, n0, K, 0, tid);

    for (int kt = 0; kt < KT; kt++) {
        asm volatile("cp.async.wait_group 0;" ::: "memory");
        __syncthreads();
        if (kt + 1 < KT)
            issue_stage(sbase + ((kt + 1) & 1) * STAGE_B, Ah_g, Bh_g, Bl_g,
                        m0, n0, K, (kt + 1) << 5, tid);

        const uint32_t stoff = (kt & 1) * STAGE_B;
        const uint32_t abase = sbase + stoff + a_lane_off;
        const uint32_t bbase = sbase + stoff + TILE_B + b_lane_off;

        #pragma unroll
        for (int ks = 0; ks < 2; ks++) {
            const uint32_t ak = abase + ks * 32;
            const uint32_t bk = bbase + ks * 32;

            uint32_t Ahf[4][4], Bhf[4][2], Blf[4][2];
            #pragma unroll
            for (int fi = 0; fi < 4; fi++)
                LDMX4(Ahf[fi], ak + fi * (16 * APITCH * 2));
            #pragma unroll
            for (int fj = 0; fj < 4; fj++)
                LDMX2(Bhf[fj], bk + fj * (8 * APITCH * 2));
            #pragma unroll
            for (int fi = 0; fi < 4; fi++)
                #pragma unroll
                for (int fj = 0; fj < 4; fj++)
                    MMA16816(acc[fi][fj], Ahf[fi], Bhf[fj]);

            #pragma unroll
            for (int fj = 0; fj < 4; fj++)
                LDMX2(Blf[fj], bk + TILE_B + fj * (8 * APITCH * 2));
            #pragma unroll
            for (int fi = 0; fi < 4; fi++)
                #pragma unroll
                for (int fj = 0; fj < 4; fj++)
                    MMA16816(acc[fi][fj], Ahf[fi], Blf[fj]);
        }
    }

    // ---- epilogue ----
    #pragma unroll
    for (int fj = 0; fj < 4; fj++) {
        const int c0 = n0 + warp_n + fj * 8 + 2 * (lane & 3);
        const bool c0ok = (c0 < N), c1ok = (c0 + 1 < N);
        const float b0 = c0ok ? bias[c0] : 0.f;
        const float b1 = c1ok ? bias[c0 + 1] : 0.f;
        #pragma unroll
        for (int fi = 0; fi < 4; fi++) {
            const int r0 = m0 + warp_m + fi * 16 + (lane >> 2);
            float v0 = acc[fi][fj][0] + b0;
            float v1 = acc[fi][fj][1] + b1;
            float v2 = acc[fi][fj][2] + b0;
            float v3 = acc[fi][fj][3] + b1;
            if (relu) {
                v0 = fmaxf(v0, 0.f); v1 = fmaxf(v1, 0.f);
                v2 = fmaxf(v2, 0.f); v3 = fmaxf(v3, 0.f);
            }
            if (Cf) {
                if (c0ok) {
                    Cf[(size_t)r0 * N + c0]       = v0;
                    Cf[(size_t)(r0 + 8) * N + c0] = v2;
                }
                if (c1ok) {
                    Cf[(size_t)r0 * N + c0 + 1]       = v1;
                    Cf[(size_t)(r0 + 8) * N + c0 + 1] = v3;
                }
            } else {
                if (c0ok) {
                    Coh[(size_t)r0 * N + c0]       = __float2half_rn(v0);
                    Coh[(size_t)(r0 + 8) * N + c0] = __float2half_rn(v2);
                }
                if (c1ok) {
                    Coh[(size_t)r0 * N + c0 + 1]       = __float2half_rn(v1);
                    Coh[(size_t)(r0 + 8) * N + c0 + 1] = __float2half_rn(v3);
                }
            }
        }
    }
}

// ---------------- embed ----------------
__global__ void embed_kernel(const int* __restrict__ q_data,
                             const int* __restrict__ target,
                             const float* __restrict__ pe,
                             const float* __restrict__ q_emb,
                             const float* __restrict__ qa_emb) {
    size_t idx = (size_t)blockIdx.x * blockDim.x + threadIdx.x;
    if (idx >= (size_t)Mr * Dc) return;
    int bs = (int)(idx / Dc);
    int d  = (int)(idx % Dc);
    int s  = bs % Sc;
    float qe = q_emb[(size_t)q_data[bs] * Dc + d];
    float p  = pe[(size_t)s * Dc + d];
    float x  = qe + p;
    float y  = qa_emb[(size_t)target[bs] * Dc + d] + qe + p;
    g_qe[idx] = qe;
    g_x [idx] = x;
    g_xh[idx] = __float2half_rn(x);
    g_yh[idx] = __float2half_rn(y);
}

// ---------------- flash attention (fp32 in, fp16 hi out) ----------------
__global__ __launch_bounds__(256)
void attn_kernel() {
    const int qt = blockIdx.x, hh = blockIdx.y, b = blockIdx.z;
    const int tid = threadIdx.x;
    const int r = tid >> 2;
    const int p = tid & 3;
    const int i = qt * 64 + r;
    const float scale = 0.125f;

    __shared__ float Kt[64][64];
    __shared__ float Vt[64][64];

    float q[16];
    {
        const float* qp = g_K + ((size_t)(b * Sc + i)) * Dc + hh * DKc + p * 16;
        #pragma unroll
        for (int w = 0; w < 4; w++) {
            float4 v = *(const float4*)(qp + w * 4);
            q[w * 4 + 0] = v.x; q[w * 4 + 1] = v.y;
            q[w * 4 + 2] = v.z; q[w * 4 + 3] = v.w;
        }
    }

    float m_run = -1e30f, l_run = 0.f;
    float o[16];
    #pragma unroll
    for (int d = 0; d < 16; d++) o[d] = 0.f;

    for (int jt = 0; jt <= qt; jt++) {
        const size_t base = ((size_t)(b * Sc + jt * 64 + r)) * Dc + hh * DKc + p * 16;
        #pragma unroll
        for (int w = 0; w < 4; w++) {
            *(float4*)&Kt[r][p * 16 + w * 4] = *(const float4*)(g_K + base + w * 4);
            *(float4*)&Vt[r][p * 16 + w * 4] = *(const float4*)(g_V + base + w * 4);
        }
        __syncthreads();

        for (int j = 0; j < 64; j++) {
            float s = 0.f;
            #pragma unroll
            for (int d = 0; d < 16; d++) s += q[d] * Kt[j][p * 16 + d];
            s += __shfl_xor_sync(0xffffffffu, s, 1);
            s += __shfl_xor_sync(0xffffffffu, s, 2);
            s *= scale;
            if (jt * 64 + j < i) {
                float m_new = fmaxf(m_run, s);
                float corr  = __expf(m_run - m_new);
                float pj    = __expf(s - m_new);
                l_run = l_run * corr + pj;
                #pragma unroll
                for (int d = 0; d < 16; d++)
                    o[d] = o[d] * corr + pj * Vt[j][p * 16 + d];
                m_run = m_new;
            }
        }
        __syncthreads();
    }

    float inv = (l_run > 0.f) ? (1.f / l_run) : 0.f;
    size_t ob = ((size_t)(b * Sc + i)) * Dc + hh * DKc + p * 16;
    #pragma unroll
    for (int d = 0; d < 16; d++)
        g_Oh[ob + d] = __float2half_rn(o[d] * inv);
}

// ---------------- fused add + LayerNorm (+ fp16 hi out) ----------------
__global__ __launch_bounds__(256)
void add_ln_kernel(float* __restrict__ x, const float* __restrict__ resid,
                   const float* __restrict__ g, const float* __restrict__ b) {
    const int row = blockIdx.x;
    const int tid = threadIdx.x;
    const size_t base = (size_t)row * Dc;
    float v0 = x[base + tid]       + resid[base + tid];
    float v1 = x[base + tid + 256] + resid[base + tid + 256];
    float s  = v0 + v1;
    float ss = v0 * v0 + v1 * v1;

    __shared__ float sbuf[8], ssbuf[8];
    #pragma unroll
    for (int o = 16; o > 0; o >>= 1) {
        s  += __shfl_xor_sync(0xffffffffu, s, o);
        ss += __shfl_xor_sync(0xffffffffu, ss, o);
    }
    if ((tid & 31) == 0) { sbuf[tid >> 5] = s; ssbuf[tid >> 5] = ss; }
    __syncthreads();
    if (tid < 32) {
        s  = (tid < 8) ? sbuf[tid]  : 0.f;
        ss = (tid < 8) ? ssbuf[tid] : 0.f;
        #pragma unroll
        for (int o = 4; o > 0; o >>= 1) {
            s  += __shfl_xor_sync(0xffffffffu, s, o);
            ss += __shfl_xor_sync(0xffffffffu, ss, o);
        }
        if (tid == 0) { sbuf[0] = s; ssbuf[0] = ss; }
    }
    __syncthreads();
    float mean = sbuf[0] * (1.f / 512.f);
    float var  = ssbuf[0] * (1.f / 512.f) - mean * mean;
    float rstd = rsqrtf(var + 1e-5f);
    float o0 = (v0 - mean) * rstd * g[tid]       + b[tid];
    float o1 = (v1 - mean) * rstd * g[tid + 256] + b[tid + 256];
    x[base + tid]       = o0;
    x[base + tid + 256] = o1;
    g_xh[base + tid]       = __float2half_rn(o0);
    g_xh[base + tid + 256] = __float2half_rn(o1);
}

// ---------------- concat [x | qe] -> fp16 hi ----------------
__global__ void concat_kernel() {
    size_t idx = (size_t)blockIdx.x * blockDim.x + threadIdx.x;
    if (idx >= (size_t)Mr * 2 * Dc) return;
    int bs = (int)(idx / (2 * Dc));
    int c  = (int)(idx % (2 * Dc));
    float v = (c < Dc) ? g_x[(size_t)bs * Dc + c]
                       : g_qe[(size_t)bs * Dc + (c - Dc)];
    g_Ch[idx] = __float2half_rn(v);
}

// ---------------- host ----------------
static inline void split_w(const float* W, __half* oh, __half* ol,
                           int K, int N, int Npad) {
    split_w_kernel<<<dim3(Npad / 32, K / 32), dim3(32, 8)>>>(W, oh, ol, K, N);
}
static inline void gemmF32(const __half* ah, const __half* bh, const __half* bl,
                           const float* bias, float* C, int K, int N, int Npad,
                           int relu) {
    gemm_mma_kernel<<<dim3(Npad / 128, Mr / 128), 256, GEMM_DSMEM>>>(
        ah, bh, bl, bias, C, nullptr, K, N, relu);
}
static inline void gemmF16(const __half* ah, const __half* bh, const __half* bl,
                           const float* bias, __half* oh, int K, int N, int Npad,
                           int relu) {
    gemm_mma_kernel<<<dim3(Npad / 128, Mr / 128), 256, GEMM_DSMEM>>>(
        ah, bh, bl, bias, nullptr, oh, K, N, relu);
}

extern "C" void kernel_launch(void* const* d_in, const int* in_sizes, int n_in,
                              void* d_out, int out_size) {
    const int*   q_data = (const int*)d_in[0];
    const int*   target = (const int*)d_in[1];
    const float* pe     = (const float*)d_in[2];
    const float* q_emb  = (const float*)d_in[3];
    const float* qa_emb = (const float*)d_in[4];
    const float* Wk     = (const float*)d_in[5];
    const float* bk     = (const float*)d_in[6];
    const float* Wv     = (const float*)d_in[7];
    const float* bv     = (const float*)d_in[8];
    const float* Wo     = (const float*)d_in[9];
    const float* bo     = (const float*)d_in[10];
    const float* ln1_g  = (const float*)d_in[11];
    const float* ln1_b  = (const float*)d_in[12];
    const float* W1     = (const float*)d_in[13];
    const float* b1     = (const float*)d_in[14];
    const float* W2     = (const float*)d_in[15];
    const float* b2     = (const float*)d_in[16];
    const float* ln2_g  = (const float*)d_in[17];
    const float* ln2_b  = (const float*)d_in[18];
    const float* Wout1  = (const float*)d_in[19];
    const float* bout1  = (const float*)d_in[20];
    const float* Wout2  = (const float*)d_in[21];
    const float* bout2  = (const float*)d_in[22];
    const float* Wout3  = (const float*)d_in[23];
    const float* bout3  = (const float*)d_in[24];
    float* out = (float*)d_out;

    cudaFuncSetAttribute(gemm_mma_kernel,
                         cudaFuncAttributeMaxDynamicSharedMemorySize, GEMM_DSMEM);

    float *p_x, *p_K, *p_V, *p_P;
    cudaGetSymbolAddress((void**)&p_x, g_x);
    cudaGetSymbolAddress((void**)&p_K, g_K);
    cudaGetSymbolAddress((void**)&p_V, g_V);
    cudaGetSymbolAddress((void**)&p_P, g_P);

    __half *xh, *yh, *oh, *f1h, *ch, *h1h, *h2h;
    cudaGetSymbolAddress((void**)&xh, g_xh);
    cudaGetSymbolAddress((void**)&yh, g_yh);
    cudaGetSymbolAddress((void**)&oh, g_Oh);
    cudaGetSymbolAddress((void**)&f1h, g_F1h);
    cudaGetSymbolAddress((void**)&ch, g_Ch);
    cudaGetSymbolAddress((void**)&h1h, g_H1h);
    cudaGetSymbolAddress((void**)&h2h, g_H2h);

    __half *wk_h, *wk_l, *wv_h, *wv_l, *wo_h, *wo_l, *w1_h, *w1_l, *w2_h, *w2_l;
    __half *wo1_h, *wo1_l, *wo2_h, *wo2_l, *wo3_h, *wo3_l;
    cudaGetSymbolAddress((void**)&wk_h, g_Wk_h); cudaGetSymbolAddress((void**)&wk_l, g_Wk_l);
    cudaGetSymbolAddress((void**)&wv_h, g_Wv_h); cudaGetSymbolAddress((void**)&wv_l, g_Wv_l);
    cudaGetSymbolAddress((void**)&wo_h, g_Wo_h); cudaGetSymbolAddress((void**)&wo_l, g_Wo_l);
    cudaGetSymbolAddress((void**)&w1_h, g_W1_h); cudaGetSymbolAddress((void**)&w1_l, g_W1_l);
    cudaGetSymbolAddress((void**)&w2_h, g_W2_h); cudaGetSymbolAddress((void**)&w2_l, g_W2_l);
    cudaGetSymbolAddress((void**)&wo1_h, g_Wo1_h); cudaGetSymbolAddress((void**)&wo1_l, g_Wo1_l);
    cudaGetSymbolAddress((void**)&wo2_h, g_Wo2_h); cudaGetSymbolAddress((void**)&wo2_l, g_Wo2_l);
    cudaGetSymbolAddress((void**)&wo3_h, g_Wo3_h); cudaGetSymbolAddress((void**)&wo3_l, g_Wo3_l);

    // ---- launch order: launch #6 (ncu -s 5 -c 1) is the first GEMM ----
    {
        size_t tot = (size_t)Mr * Dc;
        embed_kernel<<<(unsigned)((tot + 255) / 256), 256>>>(q_data, target, pe,
                                                             q_emb, qa_emb);   // 1
    }
    split_w(Wk, wk_h, wk_l, Dc, Dc, Dc);                                       // 2
    split_w(Wv, wv_h, wv_l, Dc, Dc, Dc);                                       // 3
    split_w(Wo, wo_h, wo_l, Dc, Dc, Dc);                                       // 4
    split_w(W1, w1_h, w1_l, Dc, DFFc, DFFc);                                   // 5
    gemmF32(xh, wk_h, wk_l, bk, p_K, Dc, Dc, Dc, 0);                           // 6 <- profiled
    split_w(W2, w2_h, w2_l, DFFc, Dc, Dc);                                     // 7

    for (int l = 1; l < Lc; l++) {
        size_t oDD = (size_t)l * Dc * Dc;
        size_t oDF = (size_t)l * Dc * DFFc;
        split_w(Wk + oDD, wk_h + oDD, wk_l + oDD, Dc, Dc, Dc);
        split_w(Wv + oDD, wv_h + oDD, wv_l + oDD, Dc, Dc, Dc);
        split_w(Wo + oDD, wo_h + oDD, wo_l + oDD, Dc, Dc, Dc);
        split_w(W1 + oDF, w1_h + oDF, w1_l + oDF, Dc, DFFc, DFFc);
        split_w(W2 + oDF, w2_h + oDF, w2_l + oDF, DFFc, Dc, Dc);
    }
    split_w(Wout1, wo1_h, wo1_l, 2 * Dc, FC1c, FC1c);
    split_w(Wout2, wo2_h, wo2_l, FC1c, FC2c, FC2c);
    split_w(Wout3, wo3_h, wo3_l, FC2c, NSKc, NSKp);

    // transformer layers (layer 0 K-proj launched above)
    for (int l = 0; l < Lc; l++) {
        size_t oDD = (size_t)l * Dc * Dc;
        size_t oDF = (size_t)l * Dc * DFFc;
        if (l > 0)
            gemmF32(xh, wk_h + oDD, wk_l + oDD, bk + l * Dc, p_K, Dc, Dc, Dc, 0);
        gemmF32(yh, wv_h + oDD, wv_l + oDD, bv + l * Dc, p_V, Dc, Dc, Dc, 0);
        attn_kernel<<<dim3(Sc / 64, Hc, Bc), 256>>>();
        gemmF32(oh, wo_h + oDD, wo_l + oDD, bo + l * Dc, p_P, Dc, Dc, Dc, 0);
        add_ln_kernel<<<Mr, 256>>>(p_x, p_P, ln1_g + l * Dc, ln1_b + l * Dc);
        gemmF16(xh, w1_h + oDF, w1_l + oDF, b1 + l * DFFc, f1h, Dc, DFFc, DFFc, 1);
        gemmF32(f1h, w2_h + oDF, w2_l + oDF, b2 + l * Dc, p_P, DFFc, Dc, Dc, 0);
        add_ln_kernel<<<Mr, 256>>>(p_x, p_P, ln2_g + l * Dc, ln2_b + l * Dc);
    }

    // head
    {
        size_t tot = (size_t)Mr * 2 * Dc;
        concat_kernel<<<(unsigned)((tot + 255) / 256), 256>>>();
    }
    gemmF16(ch, wo1_h, wo1_l, bout1, h1h, 2 * Dc, FC1c, FC1c, 1);
    gemmF16(h1h, wo2_h, wo2_l, bout2, h2h, FC1c, FC2c, FC2c, 1);
    gemmF32(h2h, wo3_h, wo3_l, bout3, out, FC2c, NSKc, NSKp, 0);
}